// round 4
// baseline (speedup 1.0000x reference)
#include <cuda_runtime.h>
#include <cuda_bf16.h>

// ---------------------------------------------------------------------------
// GNNEncoder: 2x GINEConv + global mean pool
//   N=200000 nodes, E=400000 edges, G=4096 graphs
//   dims: IN=128, HID=256, OUT=256, EDGE=16
// NOTE: edge_index / batch arrive as int32 (JAX x64 disabled).
// ---------------------------------------------------------------------------

#define N_NODES 200000
#define N_EDGES 400000
#define N_GRAPHS 4096

// Scratch (device globals: allocation-free per harness rules)
__device__ float g_aggr[(size_t)N_NODES * 256];
__device__ float g_h1  [(size_t)N_NODES * 256];
__device__ float g_tmp [(size_t)N_NODES * 256];
__device__ int   g_counts[N_GRAPHS];

// ---------------------------------------------------------------------------
// Zero fill (float4 grid-stride)
// ---------------------------------------------------------------------------
__global__ void zero_kernel(float4* __restrict__ p, long long n4) {
    long long i = (long long)blockIdx.x * blockDim.x + threadIdx.x;
    long long stride = (long long)gridDim.x * blockDim.x;
    float4 z = make_float4(0.f, 0.f, 0.f, 0.f);
    for (; i < n4; i += stride) p[i] = z;
}

// ---------------------------------------------------------------------------
// Message + scatter:  aggr[dst] += relu(x[src] + edge_attr @ We + be)
// One warp per edge. We (16 x D) staged in shared memory.
// ---------------------------------------------------------------------------
template<int D>
__global__ __launch_bounds__(256)
void msg_scatter(const float* __restrict__ xin,
                 const float* __restrict__ ea,
                 const float* __restrict__ We,
                 const float* __restrict__ be,
                 const int* __restrict__ src_idx,
                 const int* __restrict__ dst_idx,
                 float* __restrict__ aggr, int E) {
    __shared__ float sWe[16 * D];
    __shared__ float sbe[D];
    for (int i = threadIdx.x; i < 16 * D; i += blockDim.x) sWe[i] = We[i];
    for (int i = threadIdx.x; i < D; i += blockDim.x) sbe[i] = be[i];
    __syncthreads();

    const int lane = threadIdx.x & 31;
    const int wid  = threadIdx.x >> 5;
    const int wpb  = blockDim.x >> 5;

    for (int e = blockIdx.x * wpb + wid; e < E; e += gridDim.x * wpb) {
        const long long s = src_idx[e];
        const long long d = dst_idx[e];

        float eav[16];
        const float4* eap = reinterpret_cast<const float4*>(ea + (long long)e * 16);
        #pragma unroll
        for (int q = 0; q < 4; q++) {
            float4 v = eap[q];
            eav[4*q+0] = v.x; eav[4*q+1] = v.y; eav[4*q+2] = v.z; eav[4*q+3] = v.w;
        }

        const float* xrow = xin + s * D;
        float*       arow = aggr + d * D;

        #pragma unroll
        for (int c = 0; c < D / 128; c++) {
            const int j = c * 128 + lane * 4;   // fully coalesced float4 per warp
            float4 p = *reinterpret_cast<const float4*>(sbe + j);
            #pragma unroll
            for (int k = 0; k < 16; k++) {
                const float4 w = *reinterpret_cast<const float4*>(sWe + k * D + j);
                p.x = fmaf(eav[k], w.x, p.x);
                p.y = fmaf(eav[k], w.y, p.y);
                p.z = fmaf(eav[k], w.z, p.z);
                p.w = fmaf(eav[k], w.w, p.w);
            }
            const float4 xv = *reinterpret_cast<const float4*>(xrow + j);
            p.x = fmaxf(p.x + xv.x, 0.f);
            p.y = fmaxf(p.y + xv.y, 0.f);
            p.z = fmaxf(p.z + xv.z, 0.f);
            p.w = fmaxf(p.w + xv.w, 0.f);
            atomicAdd(arow + j + 0, p.x);
            atomicAdd(arow + j + 1, p.y);
            atomicAdd(arow + j + 2, p.z);
            atomicAdd(arow + j + 3, p.w);
        }
    }
}

// ---------------------------------------------------------------------------
// C[M,N] = relu( (A1 (+ A2)) @ W + bias )
// W row-major [K, N]. 128x128 block tile, BK=8, 8x8 per-thread micro-tile.
// ---------------------------------------------------------------------------
__global__ __launch_bounds__(256)
void gemm_relu(const float* __restrict__ A1, const float* __restrict__ A2,
               const float* __restrict__ W,  const float* __restrict__ bias,
               float* __restrict__ C, int M, int N, int K) {
    __shared__ float As[8][128];
    __shared__ float Bs[8][128];

    const int tid = threadIdx.x;
    const int tr  = tid >> 4;          // 0..15 -> rows tr*8..tr*8+7
    const int tc  = tid & 15;          // 0..15 -> cols tc*8..tc*8+7
    const int aRow = tid >> 1;         // 0..127
    const int aCol = (tid & 1) * 4;    // 0 or 4
    const int bRow = tid >> 5;         // 0..7
    const int bCol = (tid & 31) * 4;   // 0..124

    const long long rowBase = (long long)blockIdx.y * 128;
    const int colBase = blockIdx.x * 128;

    float acc[8][8];
    #pragma unroll
    for (int i = 0; i < 8; i++)
        #pragma unroll
        for (int j = 0; j < 8; j++) acc[i][j] = 0.f;

    const long long aR = rowBase + aRow;
    const bool aValid = aR < (long long)M;
    const float* a1p = A1 + aR * K + aCol;
    const float* a2p = A2 ? (A2 + aR * K + aCol) : nullptr;
    const float* wp  = W + (long long)bRow * N + colBase + bCol;

    for (int k0 = 0; k0 < K; k0 += 8) {
        float4 av = make_float4(0.f, 0.f, 0.f, 0.f);
        if (aValid) {
            av = *reinterpret_cast<const float4*>(a1p + k0);
            if (a2p) {
                float4 bv = *reinterpret_cast<const float4*>(a2p + k0);
                av.x += bv.x; av.y += bv.y; av.z += bv.z; av.w += bv.w;
            }
        }
        As[aCol + 0][aRow] = av.x;
        As[aCol + 1][aRow] = av.y;
        As[aCol + 2][aRow] = av.z;
        As[aCol + 3][aRow] = av.w;
        *reinterpret_cast<float4*>(&Bs[bRow][bCol]) =
            *reinterpret_cast<const float4*>(wp + (long long)k0 * N);
        __syncthreads();

        #pragma unroll
        for (int k = 0; k < 8; k++) {
            float a[8], b[8];
            *reinterpret_cast<float4*>(a)     = *reinterpret_cast<float4*>(&As[k][tr * 8]);
            *reinterpret_cast<float4*>(a + 4) = *reinterpret_cast<float4*>(&As[k][tr * 8 + 4]);
            *reinterpret_cast<float4*>(b)     = *reinterpret_cast<float4*>(&Bs[k][tc * 8]);
            *reinterpret_cast<float4*>(b + 4) = *reinterpret_cast<float4*>(&Bs[k][tc * 8 + 4]);
            #pragma unroll
            for (int i = 0; i < 8; i++)
                #pragma unroll
                for (int j = 0; j < 8; j++)
                    acc[i][j] = fmaf(a[i], b[j], acc[i][j]);
        }
        __syncthreads();
    }

    float bv[8];
    *reinterpret_cast<float4*>(bv)     = *reinterpret_cast<const float4*>(bias + colBase + tc * 8);
    *reinterpret_cast<float4*>(bv + 4) = *reinterpret_cast<const float4*>(bias + colBase + tc * 8 + 4);

    #pragma unroll
    for (int i = 0; i < 8; i++) {
        long long r = rowBase + tr * 8 + i;
        if (r >= (long long)M) break;
        float4 o0, o1;
        o0.x = fmaxf(acc[i][0] + bv[0], 0.f);
        o0.y = fmaxf(acc[i][1] + bv[1], 0.f);
        o0.z = fmaxf(acc[i][2] + bv[2], 0.f);
        o0.w = fmaxf(acc[i][3] + bv[3], 0.f);
        o1.x = fmaxf(acc[i][4] + bv[4], 0.f);
        o1.y = fmaxf(acc[i][5] + bv[5], 0.f);
        o1.z = fmaxf(acc[i][6] + bv[6], 0.f);
        o1.w = fmaxf(acc[i][7] + bv[7], 0.f);
        *reinterpret_cast<float4*>(C + r * N + colBase + tc * 8)     = o0;
        *reinterpret_cast<float4*>(C + r * N + colBase + tc * 8 + 4) = o1;
    }
}

// ---------------------------------------------------------------------------
// Global mean pool: atomic scatter sums + counts, then divide
// ---------------------------------------------------------------------------
__global__ __launch_bounds__(256)
void pool_sum(const float* __restrict__ h, const int* __restrict__ batch,
              float* __restrict__ out, int* __restrict__ counts, int Nn) {
    int warp = (blockIdx.x * blockDim.x + threadIdx.x) >> 5;
    int lane = threadIdx.x & 31;
    if (warp >= Nn) return;
    int g = batch[warp];
    const float* row = h + (long long)warp * 256;
    float* orow = out + (long long)g * 256;
    #pragma unroll
    for (int j = lane; j < 256; j += 32) atomicAdd(orow + j, row[j]);
    if (lane == 0) atomicAdd(counts + g, 1);
}

__global__ void pool_div(float* __restrict__ out, const int* __restrict__ counts) {
    int idx = blockIdx.x * blockDim.x + threadIdx.x;
    if (idx < N_GRAPHS * 256) {
        float c = fmaxf((float)counts[idx >> 8], 1.f);
        out[idx] = out[idx] / c;
    }
}

// ---------------------------------------------------------------------------
extern "C" void kernel_launch(void* const* d_in, const int* in_sizes, int n_in,
                              void* d_out, int out_size) {
    const float* x    = (const float*)d_in[0];
    const float* ea   = (const float*)d_in[1];
    const float* We1  = (const float*)d_in[2];
    const float* be1  = (const float*)d_in[3];
    const float* W1a  = (const float*)d_in[4];
    const float* b1a  = (const float*)d_in[5];
    const float* W1b  = (const float*)d_in[6];
    const float* b1b  = (const float*)d_in[7];
    const float* We2  = (const float*)d_in[8];
    const float* be2  = (const float*)d_in[9];
    const float* W2a  = (const float*)d_in[10];
    const float* b2a  = (const float*)d_in[11];
    const float* W2b  = (const float*)d_in[12];
    const float* b2b  = (const float*)d_in[13];
    const int* eidx   = (const int*)d_in[14];   // int32: JAX x64 disabled
    const int* batch  = (const int*)d_in[15];   // int32
    float* out = (float*)d_out;

    float *aggr, *h1, *tmp;
    int* counts;
    cudaGetSymbolAddress((void**)&aggr,   g_aggr);
    cudaGetSymbolAddress((void**)&h1,     g_h1);
    cudaGetSymbolAddress((void**)&tmp,    g_tmp);
    cudaGetSymbolAddress((void**)&counts, g_counts);

    const int Nn = N_NODES, E = N_EDGES;
    const dim3 gemm_grid(2, (Nn + 127) / 128);   // N=256 -> 2 col tiles
    const int msg_blocks = (E + 7) / 8;          // 8 warps/block, 1 warp/edge

    // ---- Layer 1 (D=128) ----
    zero_kernel<<<2048, 256>>>((float4*)aggr, (long long)Nn * 128 / 4);
    msg_scatter<128><<<msg_blocks, 256>>>(x, ea, We1, be1, eidx, eidx + E, aggr, E);
    gemm_relu<<<gemm_grid, 256>>>(x, aggr, W1a, b1a, tmp, Nn, 256, 128);
    gemm_relu<<<gemm_grid, 256>>>(tmp, nullptr, W1b, b1b, h1, Nn, 256, 256);

    // ---- Layer 2 (D=256) ----
    zero_kernel<<<2048, 256>>>((float4*)aggr, (long long)Nn * 256 / 4);
    msg_scatter<256><<<msg_blocks, 256>>>(h1, ea, We2, be2, eidx, eidx + E, aggr, E);
    gemm_relu<<<gemm_grid, 256>>>(h1, aggr, W2a, b2a, tmp, Nn, 256, 256);
    gemm_relu<<<gemm_grid, 256>>>(tmp, nullptr, W2b, b2b, h1, Nn, 256, 256);

    // ---- Global mean pool ----
    zero_kernel<<<1024, 256>>>((float4*)out, (long long)N_GRAPHS * 256 / 4);
    zero_kernel<<<4, 256>>>((float4*)counts, N_GRAPHS / 4);
    pool_sum<<<(Nn * 32 + 255) / 256, 256>>>(h1, batch, out, counts, Nn);
    pool_div<<<(N_GRAPHS * 256 + 255) / 256, 256>>>(out, counts);
}

// round 7
// speedup vs baseline: 2.0054x; 2.0054x over previous
#include <cuda_runtime.h>
#include <cuda_bf16.h>

// ---------------------------------------------------------------------------
// GNNEncoder: 2x GINEConv + global mean pool
//   N=200000 nodes, E=400000 edges, G=4096 graphs
//   dims: IN=128, HID=256, OUT=256, EDGE=16
// edge_index / batch arrive as int32 (JAX x64 disabled).
// GEMMs run on tf32 tensor cores (mma.sync m16n8k8), cp.async double-buffered.
// ---------------------------------------------------------------------------

#define N_NODES 200000
#define N_EDGES 400000
#define N_GRAPHS 4096

__device__ float g_aggr[(size_t)N_NODES * 256];
__device__ float g_h1  [(size_t)N_NODES * 256];
__device__ float g_tmp [(size_t)N_NODES * 256];
__device__ int   g_counts[N_GRAPHS];

// ---------------------------------------------------------------------------
__global__ void zero_kernel(float4* __restrict__ p, long long n4) {
    long long i = (long long)blockIdx.x * blockDim.x + threadIdx.x;
    long long stride = (long long)gridDim.x * blockDim.x;
    float4 z = make_float4(0.f, 0.f, 0.f, 0.f);
    for (; i < n4; i += stride) p[i] = z;
}

__global__ void copy_kernel(const float4* __restrict__ src, float4* __restrict__ dst,
                            long long n4) {
    long long i = (long long)blockIdx.x * blockDim.x + threadIdx.x;
    long long stride = (long long)gridDim.x * blockDim.x;
    for (; i < n4; i += stride) dst[i] = src[i];
}

// ---------------------------------------------------------------------------
// Message + scatter:  aggr[dst] += relu(x[src] + edge_attr @ We + be)
// (aggr pre-initialized with x, so after this aggr = x + sum(messages))
// ---------------------------------------------------------------------------
template<int D>
__global__ __launch_bounds__(256)
void msg_scatter(const float* __restrict__ xin,
                 const float* __restrict__ ea,
                 const float* __restrict__ We,
                 const float* __restrict__ be,
                 const int* __restrict__ src_idx,
                 const int* __restrict__ dst_idx,
                 float* __restrict__ aggr, int E) {
    __shared__ float sWe[16 * D];
    __shared__ float sbe[D];
    for (int i = threadIdx.x; i < 16 * D; i += blockDim.x) sWe[i] = We[i];
    for (int i = threadIdx.x; i < D; i += blockDim.x) sbe[i] = be[i];
    __syncthreads();

    const int lane = threadIdx.x & 31;
    const int wid  = threadIdx.x >> 5;
    const int wpb  = blockDim.x >> 5;

    for (int e = blockIdx.x * wpb + wid; e < E; e += gridDim.x * wpb) {
        const long long s = src_idx[e];
        const long long d = dst_idx[e];

        float eav[16];
        const float4* eap = reinterpret_cast<const float4*>(ea + (long long)e * 16);
        #pragma unroll
        for (int q = 0; q < 4; q++) {
            float4 v = eap[q];
            eav[4*q+0] = v.x; eav[4*q+1] = v.y; eav[4*q+2] = v.z; eav[4*q+3] = v.w;
        }

        const float* xrow = xin + s * D;
        float*       arow = aggr + d * D;

        #pragma unroll
        for (int c = 0; c < D / 128; c++) {
            const int j = c * 128 + lane * 4;
            float4 p = *reinterpret_cast<const float4*>(sbe + j);
            #pragma unroll
            for (int k = 0; k < 16; k++) {
                const float4 w = *reinterpret_cast<const float4*>(sWe + k * D + j);
                p.x = fmaf(eav[k], w.x, p.x);
                p.y = fmaf(eav[k], w.y, p.y);
                p.z = fmaf(eav[k], w.z, p.z);
                p.w = fmaf(eav[k], w.w, p.w);
            }
            const float4 xv = *reinterpret_cast<const float4*>(xrow + j);
            p.x = fmaxf(p.x + xv.x, 0.f);
            p.y = fmaxf(p.y + xv.y, 0.f);
            p.z = fmaxf(p.z + xv.z, 0.f);
            p.w = fmaxf(p.w + xv.w, 0.f);
            atomicAdd(arow + j + 0, p.x);
            atomicAdd(arow + j + 1, p.y);
            atomicAdd(arow + j + 2, p.z);
            atomicAdd(arow + j + 3, p.w);
        }
    }
}

// ---------------------------------------------------------------------------
// tf32 tensor-core GEMM: C[M,N] = relu(A @ W + bias)
// BM=128, BN=64, BK=16. 256 thr, 8 warps (4x2), warp tile 32x32.
// A smem stride 20 floats, B stride 72 floats -> conflict-free frag loads.
// ---------------------------------------------------------------------------
__device__ __forceinline__ unsigned f2tf(float f) {
    unsigned u;
    asm("cvt.rna.tf32.f32 %0, %1;" : "=r"(u) : "f"(f));
    return u;
}
__device__ __forceinline__ void cp16(float* smem_dst, const float* gptr, int src_bytes) {
    unsigned saddr = (unsigned)__cvta_generic_to_shared(smem_dst);
    asm volatile("cp.async.cg.shared.global [%0], [%1], 16, %2;"
                 :: "r"(saddr), "l"(gptr), "r"(src_bytes));
}

#define ASTRIDE 20
#define BSTRIDE 72

__global__ __launch_bounds__(256)
void gemm_tf32(const float* __restrict__ A, const float* __restrict__ W,
               const float* __restrict__ bias, float* __restrict__ C,
               int M, int N, int K) {
    __shared__ float As[2][128 * ASTRIDE];
    __shared__ float Bs[2][16 * BSTRIDE];

    const int tid  = threadIdx.x;
    const int lane = tid & 31;
    const int wid  = tid >> 5;
    const int g    = lane >> 2;       // groupID
    const int tig  = lane & 3;        // thread in group
    const int warpM = wid >> 1;       // 0..3
    const int warpN = wid & 1;        // 0..1

    const long long rowBase = (long long)blockIdx.y * 128;
    const int colBase = blockIdx.x * 64;

    // A loader: thread t -> row t>>1, chunks {(t&1)*2, (t&1)*2+1}
    const int aRow = tid >> 1;
    const int aChunk0 = (tid & 1) * 2;
    const bool aValid = (rowBase + aRow) < (long long)M;
    const float* aSrc = A + (rowBase + aRow) * K + aChunk0 * 4;
    // B loader: thread t -> row t>>4, chunk t&15
    const int bRow = tid >> 4;
    const int bChunk = tid & 15;
    const float* bSrc = W + (long long)bRow * N + colBase + bChunk * 4;

    const int S = K >> 4;

    // prologue: stages 0,1
    #pragma unroll
    for (int s = 0; s < 2; s++) {
        const int k0 = s * 16;
        cp16(&As[s][aRow * ASTRIDE + aChunk0 * 4],     aSrc + k0,     aValid ? 16 : 0);
        cp16(&As[s][aRow * ASTRIDE + aChunk0 * 4 + 4], aSrc + k0 + 4, aValid ? 16 : 0);
        cp16(&Bs[s][bRow * BSTRIDE + bChunk * 4], bSrc + (long long)k0 * N, 16);
        asm volatile("cp.async.commit_group;");
    }

    float acc[2][4][4];
    #pragma unroll
    for (int i = 0; i < 2; i++)
        #pragma unroll
        for (int j = 0; j < 4; j++)
            #pragma unroll
            for (int r = 0; r < 4; r++) acc[i][j][r] = 0.f;

    for (int s = 0; s < S; s++) {
        asm volatile("cp.async.wait_group 1;");
        __syncthreads();

        const float* as = As[s & 1];
        const float* bs = Bs[s & 1];

        #pragma unroll
        for (int kk = 0; kk < 2; kk++) {
            const int k = kk * 8;
            unsigned af[2][4], bf[4][2];
            #pragma unroll
            for (int i = 0; i < 2; i++) {
                const int r0 = warpM * 32 + i * 16 + g;
                af[i][0] = f2tf(as[(r0)     * ASTRIDE + k + tig]);
                af[i][1] = f2tf(as[(r0 + 8) * ASTRIDE + k + tig]);
                af[i][2] = f2tf(as[(r0)     * ASTRIDE + k + tig + 4]);
                af[i][3] = f2tf(as[(r0 + 8) * ASTRIDE + k + tig + 4]);
            }
            #pragma unroll
            for (int j = 0; j < 4; j++) {
                const int c0 = warpN * 32 + j * 8 + g;
                bf[j][0] = f2tf(bs[(k + tig)     * BSTRIDE + c0]);
                bf[j][1] = f2tf(bs[(k + tig + 4) * BSTRIDE + c0]);
            }
            #pragma unroll
            for (int i = 0; i < 2; i++)
                #pragma unroll
                for (int j = 0; j < 4; j++)
                    asm volatile(
                        "mma.sync.aligned.m16n8k8.row.col.f32.tf32.tf32.f32 "
                        "{%0,%1,%2,%3}, {%4,%5,%6,%7}, {%8,%9}, {%0,%1,%2,%3};"
                        : "+f"(acc[i][j][0]), "+f"(acc[i][j][1]),
                          "+f"(acc[i][j][2]), "+f"(acc[i][j][3])
                        : "r"(af[i][0]), "r"(af[i][1]), "r"(af[i][2]), "r"(af[i][3]),
                          "r"(bf[j][0]), "r"(bf[j][1]));
        }
        __syncthreads();

        const int sn = s + 2;
        if (sn < S) {
            const int k0 = sn * 16;
            cp16(&As[sn & 1][aRow * ASTRIDE + aChunk0 * 4],     aSrc + k0,     aValid ? 16 : 0);
            cp16(&As[sn & 1][aRow * ASTRIDE + aChunk0 * 4 + 4], aSrc + k0 + 4, aValid ? 16 : 0);
            cp16(&Bs[sn & 1][bRow * BSTRIDE + bChunk * 4], bSrc + (long long)k0 * N, 16);
        }
        asm volatile("cp.async.commit_group;");
    }

    // epilogue: bias + relu + store (float2 per c-frag half)
    #pragma unroll
    for (int j = 0; j < 4; j++) {
        const int col = colBase + warpN * 32 + j * 8 + 2 * tig;
        const float2 bv = *reinterpret_cast<const float2*>(bias + col);
        #pragma unroll
        for (int i = 0; i < 2; i++) {
            const long long r0 = rowBase + warpM * 32 + i * 16 + g;
            if (r0 < (long long)M) {
                float2 o;
                o.x = fmaxf(acc[i][j][0] + bv.x, 0.f);
                o.y = fmaxf(acc[i][j][1] + bv.y, 0.f);
                *reinterpret_cast<float2*>(C + r0 * N + col) = o;
            }
            const long long r1 = r0 + 8;
            if (r1 < (long long)M) {
                float2 o;
                o.x = fmaxf(acc[i][j][2] + bv.x, 0.f);
                o.y = fmaxf(acc[i][j][3] + bv.y, 0.f);
                *reinterpret_cast<float2*>(C + r1 * N + col) = o;
            }
        }
    }
}

// ---------------------------------------------------------------------------
// Global mean pool
// ---------------------------------------------------------------------------
__global__ __launch_bounds__(256)
void pool_sum(const float* __restrict__ h, const int* __restrict__ batch,
              float* __restrict__ out, int* __restrict__ counts, int Nn) {
    int warp = (blockIdx.x * blockDim.x + threadIdx.x) >> 5;
    int lane = threadIdx.x & 31;
    if (warp >= Nn) return;
    int gidx = batch[warp];
    const float* row = h + (long long)warp * 256;
    float* orow = out + (long long)gidx * 256;
    #pragma unroll
    for (int j = lane; j < 256; j += 32) atomicAdd(orow + j, row[j]);
    if (lane == 0) atomicAdd(counts + gidx, 1);
}

__global__ void pool_div(float* __restrict__ out, const int* __restrict__ counts) {
    int idx = blockIdx.x * blockDim.x + threadIdx.x;
    if (idx < N_GRAPHS * 256) {
        float c = fmaxf((float)counts[idx >> 8], 1.f);
        out[idx] = out[idx] / c;
    }
}

// ---------------------------------------------------------------------------
extern "C" void kernel_launch(void* const* d_in, const int* in_sizes, int n_in,
                              void* d_out, int out_size) {
    const float* x    = (const float*)d_in[0];
    const float* ea   = (const float*)d_in[1];
    const float* We1  = (const float*)d_in[2];
    const float* be1  = (const float*)d_in[3];
    const float* W1a  = (const float*)d_in[4];
    const float* b1a  = (const float*)d_in[5];
    const float* W1b  = (const float*)d_in[6];
    const float* b1b  = (const float*)d_in[7];
    const float* We2  = (const float*)d_in[8];
    const float* be2  = (const float*)d_in[9];
    const float* W2a  = (const float*)d_in[10];
    const float* b2a  = (const float*)d_in[11];
    const float* W2b  = (const float*)d_in[12];
    const float* b2b  = (const float*)d_in[13];
    const int* eidx   = (const int*)d_in[14];   // int32
    const int* batch  = (const int*)d_in[15];   // int32
    float* out = (float*)d_out;

    float *aggr, *h1, *tmp;
    int* counts;
    cudaGetSymbolAddress((void**)&aggr,   g_aggr);
    cudaGetSymbolAddress((void**)&h1,     g_h1);
    cudaGetSymbolAddress((void**)&tmp,    g_tmp);
    cudaGetSymbolAddress((void**)&counts, g_counts);

    const int Nn = N_NODES, E = N_EDGES;
    const dim3 gemm_grid(4, (Nn + 127) / 128);   // BN=64 -> 4 col tiles
    const int msg_blocks = (E + 7) / 8;

    // ---- Layer 1 (D=128): aggr = x, then scatter-add messages ----
    copy_kernel<<<2048, 256>>>((const float4*)x, (float4*)aggr, (long long)Nn * 128 / 4);
    msg_scatter<128><<<msg_blocks, 256>>>(x, ea, We1, be1, eidx, eidx + E, aggr, E);
    gemm_tf32<<<gemm_grid, 256>>>(aggr, W1a, b1a, tmp, Nn, 256, 128);
    gemm_tf32<<<gemm_grid, 256>>>(tmp,  W1b, b1b, h1,  Nn, 256, 256);

    // ---- Layer 2 (D=256) ----
    copy_kernel<<<2048, 256>>>((const float4*)h1, (float4*)aggr, (long long)Nn * 256 / 4);
    msg_scatter<256><<<msg_blocks, 256>>>(h1, ea, We2, be2, eidx, eidx + E, aggr, E);
    gemm_tf32<<<gemm_grid, 256>>>(aggr, W2a, b2a, tmp, Nn, 256, 256);
    gemm_tf32<<<gemm_grid, 256>>>(tmp,  W2b, b2b, h1,  Nn, 256, 256);

    // ---- Global mean pool ----
    zero_kernel<<<1024, 256>>>((float4*)out, (long long)N_GRAPHS * 256 / 4);
    zero_kernel<<<4, 256>>>((float4*)counts, N_GRAPHS / 4);
    pool_sum<<<(Nn * 32 + 255) / 256, 256>>>(h1, batch, out, counts, Nn);
    pool_div<<<(N_GRAPHS * 256 + 255) / 256, 256>>>(out, counts);
}

// round 8
// speedup vs baseline: 2.1798x; 1.0870x over previous
#include <cuda_runtime.h>
#include <cuda_bf16.h>

// ---------------------------------------------------------------------------
// GNNEncoder: 2x GINEConv + global mean pool
//   N=200000 nodes, E=400000 edges, G=4096 graphs
//   dims: IN=128, HID=256, OUT=256, EDGE=16
// edge_index / batch arrive as int32 (JAX x64 disabled).
// GEMMs: tf32 mma.sync, 3-stage cp.async pipeline, pre-rounded weights.
// Scatter: red.global.add.v4.f32 vector reductions.
// ---------------------------------------------------------------------------

#define N_NODES 200000
#define N_EDGES 400000
#define N_GRAPHS 4096

__device__ float g_aggr[(size_t)N_NODES * 256];
__device__ float g_h1  [(size_t)N_NODES * 256];
__device__ float g_tmp [(size_t)N_NODES * 256];
__device__ float g_wr  [229376];          // tf32-rounded weights
__device__ int   g_counts[N_GRAPHS];

// weight offsets in g_wr
#define O_W1A 0
#define O_W1B 32768
#define O_W2A 98304
#define O_W2B 163840

// ---------------------------------------------------------------------------
__global__ void zero_kernel(float4* __restrict__ p, long long n4) {
    long long i = (long long)blockIdx.x * blockDim.x + threadIdx.x;
    long long stride = (long long)gridDim.x * blockDim.x;
    float4 z = make_float4(0.f, 0.f, 0.f, 0.f);
    for (; i < n4; i += stride) p[i] = z;
}

__global__ void copy_kernel(const float4* __restrict__ src, float4* __restrict__ dst,
                            long long n4) {
    long long i = (long long)blockIdx.x * blockDim.x + threadIdx.x;
    long long stride = (long long)gridDim.x * blockDim.x;
    for (; i < n4; i += stride) dst[i] = src[i];
}

__device__ __forceinline__ float roundtf(float f) {
    unsigned u;
    asm("cvt.rna.tf32.f32 %0, %1;" : "=r"(u) : "f"(f));
    return __uint_as_float(u);
}

__global__ void round_tf32_kernel(const float* __restrict__ src,
                                  float* __restrict__ dst, int n) {
    int i = blockIdx.x * blockDim.x + threadIdx.x;
    if (i < n) dst[i] = roundtf(src[i]);
}

// ---------------------------------------------------------------------------
// Message + scatter:  aggr[dst] += relu(x[src] + edge_attr @ We + be)
// (aggr pre-initialized with x). Vector reductions red.global.add.v4.f32.
// ---------------------------------------------------------------------------
template<int D>
__global__ __launch_bounds__(256)
void msg_scatter(const float* __restrict__ xin,
                 const float* __restrict__ ea,
                 const float* __restrict__ We,
                 const float* __restrict__ be,
                 const int* __restrict__ src_idx,
                 const int* __restrict__ dst_idx,
                 float* __restrict__ aggr, int E) {
    __shared__ float sWe[16 * D];
    __shared__ float sbe[D];
    for (int i = threadIdx.x; i < 16 * D; i += blockDim.x) sWe[i] = We[i];
    for (int i = threadIdx.x; i < D; i += blockDim.x) sbe[i] = be[i];
    __syncthreads();

    const int lane = threadIdx.x & 31;
    const int wid  = threadIdx.x >> 5;
    const int wpb  = blockDim.x >> 5;

    for (int e = blockIdx.x * wpb + wid; e < E; e += gridDim.x * wpb) {
        const long long s = src_idx[e];
        const long long d = dst_idx[e];

        float eav[16];
        const float4* eap = reinterpret_cast<const float4*>(ea + (long long)e * 16);
        #pragma unroll
        for (int q = 0; q < 4; q++) {
            float4 v = eap[q];
            eav[4*q+0] = v.x; eav[4*q+1] = v.y; eav[4*q+2] = v.z; eav[4*q+3] = v.w;
        }

        const float* xrow = xin + s * D;
        float*       arow = aggr + d * D;

        #pragma unroll
        for (int c = 0; c < D / 128; c++) {
            const int j = c * 128 + lane * 4;
            float4 p = *reinterpret_cast<const float4*>(sbe + j);
            #pragma unroll
            for (int k = 0; k < 16; k++) {
                const float4 w = *reinterpret_cast<const float4*>(sWe + k * D + j);
                p.x = fmaf(eav[k], w.x, p.x);
                p.y = fmaf(eav[k], w.y, p.y);
                p.z = fmaf(eav[k], w.z, p.z);
                p.w = fmaf(eav[k], w.w, p.w);
            }
            const float4 xv = *reinterpret_cast<const float4*>(xrow + j);
            p.x = fmaxf(p.x + xv.x, 0.f);
            p.y = fmaxf(p.y + xv.y, 0.f);
            p.z = fmaxf(p.z + xv.z, 0.f);
            p.w = fmaxf(p.w + xv.w, 0.f);
            asm volatile("red.global.add.v4.f32 [%0], {%1,%2,%3,%4};"
                         :: "l"(arow + j), "f"(p.x), "f"(p.y), "f"(p.z), "f"(p.w)
                         : "memory");
        }
    }
}

// ---------------------------------------------------------------------------
// tf32 tensor-core GEMM: C[M,N] = relu(A @ W + bias), optional dup-store C2.
// BM=128, BN=64, BK=16, 3-stage cp.async, one barrier per stage.
// W must be pre-rounded to tf32 (raw-bit fragment loads, no cvt).
// ---------------------------------------------------------------------------
__device__ __forceinline__ unsigned f2tf(float f) {
    unsigned u;
    asm("cvt.rna.tf32.f32 %0, %1;" : "=r"(u) : "f"(f));
    return u;
}
__device__ __forceinline__ void cp16(float* smem_dst, const float* gptr, int src_bytes) {
    unsigned saddr = (unsigned)__cvta_generic_to_shared(smem_dst);
    asm volatile("cp.async.cg.shared.global [%0], [%1], 16, %2;"
                 :: "r"(saddr), "l"(gptr), "r"(src_bytes));
}

#define ASTRIDE 20
#define BSTRIDE 72

__global__ __launch_bounds__(256)
void gemm_tf32(const float* __restrict__ A, const float* __restrict__ W,
               const float* __restrict__ bias, float* __restrict__ C,
               float* __restrict__ C2, int M, int N, int K) {
    __shared__ float As[3][128 * ASTRIDE];
    __shared__ float Bs[3][16 * BSTRIDE];

    const int tid  = threadIdx.x;
    const int lane = tid & 31;
    const int wid  = tid >> 5;
    const int g    = lane >> 2;
    const int tig  = lane & 3;
    const int warpM = wid >> 1;       // 0..3
    const int warpN = wid & 1;        // 0..1

    const long long rowBase = (long long)blockIdx.y * 128;
    const int colBase = blockIdx.x * 64;

    const int aRow = tid >> 1;
    const int aChunk0 = (tid & 1) * 2;
    const bool aValid = (rowBase + aRow) < (long long)M;
    const float* aSrc = A + (rowBase + aRow) * K + aChunk0 * 4;
    const int bRow = tid >> 4;
    const int bChunk = tid & 15;
    const float* bSrc = W + (long long)bRow * N + colBase + bChunk * 4;

    const int S = K >> 4;

    // prologue: stages 0,1
    #pragma unroll
    for (int s = 0; s < 2; s++) {
        const int k0 = s * 16;
        cp16(&As[s][aRow * ASTRIDE + aChunk0 * 4],     aSrc + k0,     aValid ? 16 : 0);
        cp16(&As[s][aRow * ASTRIDE + aChunk0 * 4 + 4], aSrc + k0 + 4, aValid ? 16 : 0);
        cp16(&Bs[s][bRow * BSTRIDE + bChunk * 4], bSrc + (long long)k0 * N, 16);
        asm volatile("cp.async.commit_group;");
    }

    float acc[2][4][4];
    #pragma unroll
    for (int i = 0; i < 2; i++)
        #pragma unroll
        for (int j = 0; j < 4; j++)
            #pragma unroll
            for (int r = 0; r < 4; r++) acc[i][j][r] = 0.f;

    for (int s = 0; s < S; s++) {
        asm volatile("cp.async.wait_group 1;");
        __syncthreads();

        // prefetch stage s+2 into buffer (s+2)%3 (== (s-1)%3: all reads retired
        // by the barrier above); overlaps with compute of stage s below.
        const int sn = s + 2;
        if (sn < S) {
            const int buf = sn % 3;
            const int k0 = sn * 16;
            cp16(&As[buf][aRow * ASTRIDE + aChunk0 * 4],     aSrc + k0,     aValid ? 16 : 0);
            cp16(&As[buf][aRow * ASTRIDE + aChunk0 * 4 + 4], aSrc + k0 + 4, aValid ? 16 : 0);
            cp16(&Bs[buf][bRow * BSTRIDE + bChunk * 4], bSrc + (long long)k0 * N, 16);
        }
        asm volatile("cp.async.commit_group;");

        const float* as = As[s % 3];
        const float* bs = Bs[s % 3];

        #pragma unroll
        for (int kk = 0; kk < 2; kk++) {
            const int k = kk * 8;
            unsigned af[2][4], bf[4][2];
            #pragma unroll
            for (int i = 0; i < 2; i++) {
                const int r0 = warpM * 32 + i * 16 + g;
                af[i][0] = f2tf(as[(r0)     * ASTRIDE + k + tig]);
                af[i][1] = f2tf(as[(r0 + 8) * ASTRIDE + k + tig]);
                af[i][2] = f2tf(as[(r0)     * ASTRIDE + k + tig + 4]);
                af[i][3] = f2tf(as[(r0 + 8) * ASTRIDE + k + tig + 4]);
            }
            #pragma unroll
            for (int j = 0; j < 4; j++) {
                const int c0 = warpN * 32 + j * 8 + g;
                bf[j][0] = __float_as_uint(bs[(k + tig)     * BSTRIDE + c0]);
                bf[j][1] = __float_as_uint(bs[(k + tig + 4) * BSTRIDE + c0]);
            }
            #pragma unroll
            for (int i = 0; i < 2; i++)
                #pragma unroll
                for (int j = 0; j < 4; j++)
                    asm volatile(
                        "mma.sync.aligned.m16n8k8.row.col.f32.tf32.tf32.f32 "
                        "{%0,%1,%2,%3}, {%4,%5,%6,%7}, {%8,%9}, {%0,%1,%2,%3};"
                        : "+f"(acc[i][j][0]), "+f"(acc[i][j][1]),
                          "+f"(acc[i][j][2]), "+f"(acc[i][j][3])
                        : "r"(af[i][0]), "r"(af[i][1]), "r"(af[i][2]), "r"(af[i][3]),
                          "r"(bf[j][0]), "r"(bf[j][1]));
        }
    }

    // epilogue: bias + relu + store (optional dup store to C2)
    #pragma unroll
    for (int j = 0; j < 4; j++) {
        const int col = colBase + warpN * 32 + j * 8 + 2 * tig;
        const float2 bv = *reinterpret_cast<const float2*>(bias + col);
        #pragma unroll
        for (int i = 0; i < 2; i++) {
            const long long r0 = rowBase + warpM * 32 + i * 16 + g;
            if (r0 < (long long)M) {
                float2 o;
                o.x = fmaxf(acc[i][j][0] + bv.x, 0.f);
                o.y = fmaxf(acc[i][j][1] + bv.y, 0.f);
                *reinterpret_cast<float2*>(C + r0 * N + col) = o;
                if (C2) *reinterpret_cast<float2*>(C2 + r0 * N + col) = o;
            }
            const long long r1 = r0 + 8;
            if (r1 < (long long)M) {
                float2 o;
                o.x = fmaxf(acc[i][j][2] + bv.x, 0.f);
                o.y = fmaxf(acc[i][j][3] + bv.y, 0.f);
                *reinterpret_cast<float2*>(C + r1 * N + col) = o;
                if (C2) *reinterpret_cast<float2*>(C2 + r1 * N + col) = o;
            }
        }
    }
}

// ---------------------------------------------------------------------------
// Global mean pool (vector reductions)
// ---------------------------------------------------------------------------
__global__ __launch_bounds__(256)
void pool_sum(const float* __restrict__ h, const int* __restrict__ batch,
              float* __restrict__ out, int* __restrict__ counts, int Nn) {
    int warp = (blockIdx.x * blockDim.x + threadIdx.x) >> 5;
    int lane = threadIdx.x & 31;
    if (warp >= Nn) return;
    int gidx = batch[warp];
    const float* row = h + (long long)warp * 256;
    float* orow = out + (long long)gidx * 256;
    #pragma unroll
    for (int c = 0; c < 2; c++) {
        const int j = c * 128 + lane * 4;
        const float4 v = *reinterpret_cast<const float4*>(row + j);
        asm volatile("red.global.add.v4.f32 [%0], {%1,%2,%3,%4};"
                     :: "l"(orow + j), "f"(v.x), "f"(v.y), "f"(v.z), "f"(v.w)
                     : "memory");
    }
    if (lane == 0) atomicAdd(counts + gidx, 1);
}

__global__ void pool_div(float* __restrict__ out, const int* __restrict__ counts) {
    int idx = blockIdx.x * blockDim.x + threadIdx.x;
    if (idx < N_GRAPHS * 256) {
        float c = fmaxf((float)counts[idx >> 8], 1.f);
        out[idx] = out[idx] / c;
    }
}

// ---------------------------------------------------------------------------
extern "C" void kernel_launch(void* const* d_in, const int* in_sizes, int n_in,
                              void* d_out, int out_size) {
    const float* x    = (const float*)d_in[0];
    const float* ea   = (const float*)d_in[1];
    const float* We1  = (const float*)d_in[2];
    const float* be1  = (const float*)d_in[3];
    const float* W1a  = (const float*)d_in[4];
    const float* b1a  = (const float*)d_in[5];
    const float* W1b  = (const float*)d_in[6];
    const float* b1b  = (const float*)d_in[7];
    const float* We2  = (const float*)d_in[8];
    const float* be2  = (const float*)d_in[9];
    const float* W2a  = (const float*)d_in[10];
    const float* b2a  = (const float*)d_in[11];
    const float* W2b  = (const float*)d_in[12];
    const float* b2b  = (const float*)d_in[13];
    const int* eidx   = (const int*)d_in[14];   // int32
    const int* batch  = (const int*)d_in[15];   // int32
    float* out = (float*)d_out;

    float *aggr, *h1, *tmp, *wr;
    int* counts;
    cudaGetSymbolAddress((void**)&aggr,   g_aggr);
    cudaGetSymbolAddress((void**)&h1,     g_h1);
    cudaGetSymbolAddress((void**)&tmp,    g_tmp);
    cudaGetSymbolAddress((void**)&wr,     g_wr);
    cudaGetSymbolAddress((void**)&counts, g_counts);

    const int Nn = N_NODES, E = N_EDGES;
    const dim3 gemm_grid(4, (Nn + 127) / 128);   // BN=64 -> 4 col tiles
    const int msg_blocks = (E + 7) / 8;

    // Pre-round weights to tf32 (tiny)
    round_tf32_kernel<<<128, 256>>>(W1a, wr + O_W1A, 128 * 256);
    round_tf32_kernel<<<256, 256>>>(W1b, wr + O_W1B, 256 * 256);
    round_tf32_kernel<<<256, 256>>>(W2a, wr + O_W2A, 256 * 256);
    round_tf32_kernel<<<256, 256>>>(W2b, wr + O_W2B, 256 * 256);

    // ---- Layer 1 (D=128): aggr = x, then scatter-add messages ----
    copy_kernel<<<2048, 256>>>((const float4*)x, (float4*)aggr, (long long)Nn * 128 / 4);
    msg_scatter<128><<<msg_blocks, 256>>>(x, ea, We1, be1, eidx, eidx + E, aggr, E);
    gemm_tf32<<<gemm_grid, 256>>>(aggr, wr + O_W1A, b1a, tmp, nullptr, Nn, 256, 128);
    // final layer-1 GEMM dup-stores into aggr (feeds layer-2 residual base)
    gemm_tf32<<<gemm_grid, 256>>>(tmp, wr + O_W1B, b1b, h1, aggr, Nn, 256, 256);

    // ---- Layer 2 (D=256) ----
    msg_scatter<256><<<msg_blocks, 256>>>(h1, ea, We2, be2, eidx, eidx + E, aggr, E);
    gemm_tf32<<<gemm_grid, 256>>>(aggr, wr + O_W2A, b2a, tmp, nullptr, Nn, 256, 256);
    gemm_tf32<<<gemm_grid, 256>>>(tmp, wr + O_W2B, b2b, h1, nullptr, Nn, 256, 256);

    // ---- Global mean pool ----
    zero_kernel<<<1024, 256>>>((float4*)out, (long long)N_GRAPHS * 256 / 4);
    zero_kernel<<<4, 256>>>((float4*)counts, N_GRAPHS / 4);
    pool_sum<<<(Nn * 32 + 255) / 256, 256>>>(h1, batch, out, counts, Nn);
    pool_div<<<(N_GRAPHS * 256 + 255) / 256, 256>>>(out, counts);
}

// round 9
// speedup vs baseline: 2.2588x; 1.0362x over previous
#include <cuda_runtime.h>
#include <cuda_bf16.h>

// ---------------------------------------------------------------------------
// GNNEncoder: 2x GINEConv + global mean pool
//   N=200000 nodes, E=400000 edges, G=4096 graphs
//   dims: IN=128, HID=256, OUT=256, EDGE=16
// edge_index / batch arrive as int32 (JAX x64 disabled).
// GEMMs: tf32 mma.sync, BM=128/BN=128 tiles, 3-stage cp.async pipeline,
//        pre-rounded weights + pre-rounded intermediate activations.
// Scatter: red.global.add.v4.f32 vector reductions, warp-per-128-col-chunk.
// ---------------------------------------------------------------------------

#define N_NODES 200000
#define N_EDGES 400000
#define N_GRAPHS 4096

__device__ float g_aggr[(size_t)N_NODES * 256];
__device__ float g_h1  [(size_t)N_NODES * 256];
__device__ float g_tmp [(size_t)N_NODES * 256];
__device__ float g_wr  [229376];          // tf32-rounded weights
__device__ int   g_counts[N_GRAPHS];

#define O_W1A 0
#define O_W1B 32768
#define O_W2A 98304
#define O_W2B 163840

// ---------------------------------------------------------------------------
__global__ void zero_kernel(float4* __restrict__ p, long long n4) {
    long long i = (long long)blockIdx.x * blockDim.x + threadIdx.x;
    long long stride = (long long)gridDim.x * blockDim.x;
    float4 z = make_float4(0.f, 0.f, 0.f, 0.f);
    for (; i < n4; i += stride) p[i] = z;
}

__global__ void copy_kernel(const float4* __restrict__ src, float4* __restrict__ dst,
                            long long n4) {
    long long i = (long long)blockIdx.x * blockDim.x + threadIdx.x;
    long long stride = (long long)gridDim.x * blockDim.x;
    for (; i < n4; i += stride) dst[i] = src[i];
}

__device__ __forceinline__ float roundtf(float f) {
    unsigned u;
    asm("cvt.rna.tf32.f32 %0, %1;" : "=r"(u) : "f"(f));
    return __uint_as_float(u);
}

__global__ void round_tf32_kernel(const float* __restrict__ src,
                                  float* __restrict__ dst, int n) {
    int i = blockIdx.x * blockDim.x + threadIdx.x;
    if (i < n) dst[i] = roundtf(src[i]);
}

// ---------------------------------------------------------------------------
// Message + scatter:  aggr[dst] += relu(x[src] + edge_attr @ We + be)
// (aggr pre-initialized with x). One warp per 128-col chunk per edge.
// ---------------------------------------------------------------------------
template<int D>
__global__ __launch_bounds__(256)
void msg_scatter(const float* __restrict__ xin,
                 const float* __restrict__ ea,
                 const float* __restrict__ We,
                 const float* __restrict__ be,
                 const int* __restrict__ src_idx,
                 const int* __restrict__ dst_idx,
                 float* __restrict__ aggr, int E) {
    __shared__ float sWe[16 * D];
    __shared__ float sbe[D];
    for (int i = threadIdx.x; i < 16 * D; i += blockDim.x) sWe[i] = We[i];
    for (int i = threadIdx.x; i < D; i += blockDim.x) sbe[i] = be[i];
    __syncthreads();

    const int lane = threadIdx.x & 31;
    const int wid  = threadIdx.x >> 5;
    const int wpb  = blockDim.x >> 5;
    const int CH   = D / 128;
    const int NT   = E * CH;

    for (int t = blockIdx.x * wpb + wid; t < NT; t += gridDim.x * wpb) {
        int e, chunk;
        if (CH == 1) { e = t; chunk = 0; }
        else         { chunk = (t >= E) ? 1 : 0; e = t - chunk * E; }

        const long long s = src_idx[e];
        const long long d = dst_idx[e];

        float eav[16];
        const float4* eap = reinterpret_cast<const float4*>(ea + (long long)e * 16);
        #pragma unroll
        for (int q = 0; q < 4; q++) {
            float4 v = eap[q];
            eav[4*q+0] = v.x; eav[4*q+1] = v.y; eav[4*q+2] = v.z; eav[4*q+3] = v.w;
        }

        const int j = chunk * 128 + lane * 4;
        float4 p = *reinterpret_cast<const float4*>(sbe + j);
        #pragma unroll
        for (int k = 0; k < 16; k++) {
            const float4 w = *reinterpret_cast<const float4*>(sWe + k * D + j);
            p.x = fmaf(eav[k], w.x, p.x);
            p.y = fmaf(eav[k], w.y, p.y);
            p.z = fmaf(eav[k], w.z, p.z);
            p.w = fmaf(eav[k], w.w, p.w);
        }
        const float4 xv = *reinterpret_cast<const float4*>(xin + s * D + j);
        p.x = fmaxf(p.x + xv.x, 0.f);
        p.y = fmaxf(p.y + xv.y, 0.f);
        p.z = fmaxf(p.z + xv.z, 0.f);
        p.w = fmaxf(p.w + xv.w, 0.f);
        asm volatile("red.global.add.v4.f32 [%0], {%1,%2,%3,%4};"
                     :: "l"(aggr + d * D + j), "f"(p.x), "f"(p.y), "f"(p.z), "f"(p.w)
                     : "memory");
    }
}

// ---------------------------------------------------------------------------
// tf32 tensor-core GEMM: C[M,N] = relu(A @ W + bias), optional dup-store C2.
// BM=128, BN=128, BK=16. 8 warps (2x4), warp tile 64x32. 3-stage cp.async.
// AROUND: A already tf32-rounded (raw-bit loads). CROUND: round C on store.
// ---------------------------------------------------------------------------
__device__ __forceinline__ unsigned f2tf(float f) {
    unsigned u;
    asm("cvt.rna.tf32.f32 %0, %1;" : "=r"(u) : "f"(f));
    return u;
}
__device__ __forceinline__ void cp16(float* smem_dst, const float* gptr, int src_bytes) {
    unsigned saddr = (unsigned)__cvta_generic_to_shared(smem_dst);
    asm volatile("cp.async.cg.shared.global [%0], [%1], 16, %2;"
                 :: "r"(saddr), "l"(gptr), "r"(src_bytes));
}

#define ASTRIDE 20
#define BSTRIDE 136

template<bool AROUND, bool CROUND>
__global__ __launch_bounds__(256)
void gemm_tf32(const float* __restrict__ A, const float* __restrict__ W,
               const float* __restrict__ bias, float* __restrict__ C,
               float* __restrict__ C2, int M, int N, int K) {
    __shared__ float As[3][128 * ASTRIDE];
    __shared__ float Bs[3][16 * BSTRIDE];

    const int tid  = threadIdx.x;
    const int lane = tid & 31;
    const int wid  = tid >> 5;
    const int g    = lane >> 2;
    const int tig  = lane & 3;
    const int warpM = wid >> 2;       // 0..1 -> 64 rows each
    const int warpN = wid & 3;        // 0..3 -> 32 cols each

    const long long rowBase = (long long)blockIdx.y * 128;
    const int colBase = blockIdx.x * 128;

    // A loader: thread t -> row t>>1, two float4 chunks
    const int aRow = tid >> 1;
    const int aChunk0 = (tid & 1) * 2;
    const bool aValid = (rowBase + aRow) < (long long)M;
    const float* aSrc = A + (rowBase + aRow) * K + aChunk0 * 4;
    // B loader: thread t -> row t>>4, chunks (t&15), (t&15)+16
    const int bRow = tid >> 4;
    const int bChunk = tid & 15;
    const float* bSrc = W + (long long)bRow * N + colBase + bChunk * 4;

    const int S = K >> 4;

    #pragma unroll
    for (int s = 0; s < 2; s++) {
        const int k0 = s * 16;
        cp16(&As[s][aRow * ASTRIDE + aChunk0 * 4],     aSrc + k0,     aValid ? 16 : 0);
        cp16(&As[s][aRow * ASTRIDE + aChunk0 * 4 + 4], aSrc + k0 + 4, aValid ? 16 : 0);
        cp16(&Bs[s][bRow * BSTRIDE + bChunk * 4],        bSrc + (long long)k0 * N,      16);
        cp16(&Bs[s][bRow * BSTRIDE + (bChunk + 16) * 4], bSrc + (long long)k0 * N + 64, 16);
        asm volatile("cp.async.commit_group;");
    }

    float acc[4][4][4];
    #pragma unroll
    for (int i = 0; i < 4; i++)
        #pragma unroll
        for (int j = 0; j < 4; j++)
            #pragma unroll
            for (int r = 0; r < 4; r++) acc[i][j][r] = 0.f;

    for (int s = 0; s < S; s++) {
        asm volatile("cp.async.wait_group 1;");
        __syncthreads();

        const int sn = s + 2;
        if (sn < S) {
            const int buf = sn % 3;
            const int k0 = sn * 16;
            cp16(&As[buf][aRow * ASTRIDE + aChunk0 * 4],     aSrc + k0,     aValid ? 16 : 0);
            cp16(&As[buf][aRow * ASTRIDE + aChunk0 * 4 + 4], aSrc + k0 + 4, aValid ? 16 : 0);
            cp16(&Bs[buf][bRow * BSTRIDE + bChunk * 4],        bSrc + (long long)k0 * N,      16);
            cp16(&Bs[buf][bRow * BSTRIDE + (bChunk + 16) * 4], bSrc + (long long)k0 * N + 64, 16);
        }
        asm volatile("cp.async.commit_group;");

        const float* as = As[s % 3];
        const float* bs = Bs[s % 3];

        #pragma unroll
        for (int kk = 0; kk < 2; kk++) {
            const int k = kk * 8;
            unsigned af[4][4], bf[4][2];
            #pragma unroll
            for (int i = 0; i < 4; i++) {
                const int r0 = warpM * 64 + i * 16 + g;
                if (AROUND) {
                    af[i][0] = __float_as_uint(as[(r0)     * ASTRIDE + k + tig]);
                    af[i][1] = __float_as_uint(as[(r0 + 8) * ASTRIDE + k + tig]);
                    af[i][2] = __float_as_uint(as[(r0)     * ASTRIDE + k + tig + 4]);
                    af[i][3] = __float_as_uint(as[(r0 + 8) * ASTRIDE + k + tig + 4]);
                } else {
                    af[i][0] = f2tf(as[(r0)     * ASTRIDE + k + tig]);
                    af[i][1] = f2tf(as[(r0 + 8) * ASTRIDE + k + tig]);
                    af[i][2] = f2tf(as[(r0)     * ASTRIDE + k + tig + 4]);
                    af[i][3] = f2tf(as[(r0 + 8) * ASTRIDE + k + tig + 4]);
                }
            }
            #pragma unroll
            for (int j = 0; j < 4; j++) {
                const int c0 = warpN * 32 + j * 8 + g;
                bf[j][0] = __float_as_uint(bs[(k + tig)     * BSTRIDE + c0]);
                bf[j][1] = __float_as_uint(bs[(k + tig + 4) * BSTRIDE + c0]);
            }
            #pragma unroll
            for (int i = 0; i < 4; i++)
                #pragma unroll
                for (int j = 0; j < 4; j++)
                    asm volatile(
                        "mma.sync.aligned.m16n8k8.row.col.f32.tf32.tf32.f32 "
                        "{%0,%1,%2,%3}, {%4,%5,%6,%7}, {%8,%9}, {%0,%1,%2,%3};"
                        : "+f"(acc[i][j][0]), "+f"(acc[i][j][1]),
                          "+f"(acc[i][j][2]), "+f"(acc[i][j][3])
                        : "r"(af[i][0]), "r"(af[i][1]), "r"(af[i][2]), "r"(af[i][3]),
                          "r"(bf[j][0]), "r"(bf[j][1]));
        }
    }

    // epilogue: bias + relu (+ optional tf32 round) + store
    #pragma unroll
    for (int j = 0; j < 4; j++) {
        const int col = colBase + warpN * 32 + j * 8 + 2 * tig;
        const float2 bv = *reinterpret_cast<const float2*>(bias + col);
        #pragma unroll
        for (int i = 0; i < 4; i++) {
            const long long r0 = rowBase + warpM * 64 + i * 16 + g;
            if (r0 < (long long)M) {
                float2 o;
                o.x = fmaxf(acc[i][j][0] + bv.x, 0.f);
                o.y = fmaxf(acc[i][j][1] + bv.y, 0.f);
                if (CROUND) { o.x = roundtf(o.x); o.y = roundtf(o.y); }
                *reinterpret_cast<float2*>(C + r0 * N + col) = o;
                if (C2) *reinterpret_cast<float2*>(C2 + r0 * N + col) = o;
            }
            const long long r1 = r0 + 8;
            if (r1 < (long long)M) {
                float2 o;
                o.x = fmaxf(acc[i][j][2] + bv.x, 0.f);
                o.y = fmaxf(acc[i][j][3] + bv.y, 0.f);
                if (CROUND) { o.x = roundtf(o.x); o.y = roundtf(o.y); }
                *reinterpret_cast<float2*>(C + r1 * N + col) = o;
                if (C2) *reinterpret_cast<float2*>(C2 + r1 * N + col) = o;
            }
        }
    }
}

// ---------------------------------------------------------------------------
// Global mean pool (vector reductions)
// ---------------------------------------------------------------------------
__global__ __launch_bounds__(256)
void pool_sum(const float* __restrict__ h, const int* __restrict__ batch,
              float* __restrict__ out, int* __restrict__ counts, int Nn) {
    int warp = (blockIdx.x * blockDim.x + threadIdx.x) >> 5;
    int lane = threadIdx.x & 31;
    if (warp >= Nn) return;
    int gidx = batch[warp];
    const float* row = h + (long long)warp * 256;
    float* orow = out + (long long)gidx * 256;
    #pragma unroll
    for (int c = 0; c < 2; c++) {
        const int j = c * 128 + lane * 4;
        const float4 v = *reinterpret_cast<const float4*>(row + j);
        asm volatile("red.global.add.v4.f32 [%0], {%1,%2,%3,%4};"
                     :: "l"(orow + j), "f"(v.x), "f"(v.y), "f"(v.z), "f"(v.w)
                     : "memory");
    }
    if (lane == 0) atomicAdd(counts + gidx, 1);
}

__global__ void pool_div(float* __restrict__ out, const int* __restrict__ counts) {
    int idx = blockIdx.x * blockDim.x + threadIdx.x;
    if (idx < N_GRAPHS * 256) {
        float c = fmaxf((float)counts[idx >> 8], 1.f);
        out[idx] = out[idx] / c;
    }
}

// ---------------------------------------------------------------------------
extern "C" void kernel_launch(void* const* d_in, const int* in_sizes, int n_in,
                              void* d_out, int out_size) {
    const float* x    = (const float*)d_in[0];
    const float* ea   = (const float*)d_in[1];
    const float* We1  = (const float*)d_in[2];
    const float* be1  = (const float*)d_in[3];
    const float* W1a  = (const float*)d_in[4];
    const float* b1a  = (const float*)d_in[5];
    const float* W1b  = (const float*)d_in[6];
    const float* b1b  = (const float*)d_in[7];
    const float* We2  = (const float*)d_in[8];
    const float* be2  = (const float*)d_in[9];
    const float* W2a  = (const float*)d_in[10];
    const float* b2a  = (const float*)d_in[11];
    const float* W2b  = (const float*)d_in[12];
    const float* b2b  = (const float*)d_in[13];
    const int* eidx   = (const int*)d_in[14];   // int32
    const int* batch  = (const int*)d_in[15];   // int32
    float* out = (float*)d_out;

    float *aggr, *h1, *tmp, *wr;
    int* counts;
    cudaGetSymbolAddress((void**)&aggr,   g_aggr);
    cudaGetSymbolAddress((void**)&h1,     g_h1);
    cudaGetSymbolAddress((void**)&tmp,    g_tmp);
    cudaGetSymbolAddress((void**)&wr,     g_wr);
    cudaGetSymbolAddress((void**)&counts, g_counts);

    const int Nn = N_NODES, E = N_EDGES;
    const dim3 gemm_grid(2, (Nn + 127) / 128);   // BN=128 -> 2 col tiles

    // Pre-round weights to tf32 (tiny)
    round_tf32_kernel<<<128, 256>>>(W1a, wr + O_W1A, 128 * 256);
    round_tf32_kernel<<<256, 256>>>(W1b, wr + O_W1B, 256 * 256);
    round_tf32_kernel<<<256, 256>>>(W2a, wr + O_W2A, 256 * 256);
    round_tf32_kernel<<<256, 256>>>(W2b, wr + O_W2B, 256 * 256);

    // ---- Layer 1 (D=128): aggr = x, then scatter-add messages ----
    copy_kernel<<<2048, 256>>>((const float4*)x, (float4*)aggr, (long long)Nn * 128 / 4);
    msg_scatter<128><<<(E + 7) / 8, 256>>>(x, ea, We1, be1, eidx, eidx + E, aggr, E);
    gemm_tf32<false, true ><<<gemm_grid, 256>>>(aggr, wr + O_W1A, b1a, tmp, nullptr, Nn, 256, 128);
    // final layer-1 GEMM dup-stores into aggr (feeds layer-2 residual base)
    gemm_tf32<true,  false><<<gemm_grid, 256>>>(tmp, wr + O_W1B, b1b, h1, aggr, Nn, 256, 256);

    // ---- Layer 2 (D=256) ----
    msg_scatter<256><<<(2 * E + 7) / 8, 256>>>(h1, ea, We2, be2, eidx, eidx + E, aggr, E);
    gemm_tf32<false, true ><<<gemm_grid, 256>>>(aggr, wr + O_W2A, b2a, tmp, nullptr, Nn, 256, 256);
    gemm_tf32<true,  false><<<gemm_grid, 256>>>(tmp, wr + O_W2B, b2b, h1, nullptr, Nn, 256, 256);

    // ---- Global mean pool ----
    zero_kernel<<<1024, 256>>>((float4*)out, (long long)N_GRAPHS * 256 / 4);
    zero_kernel<<<4, 256>>>((float4*)counts, N_GRAPHS / 4);
    pool_sum<<<(Nn * 32 + 255) / 256, 256>>>(h1, batch, out, counts, Nn);
    pool_div<<<(N_GRAPHS * 256 + 255) / 256, 256>>>(out, counts);
}

// round 10
// speedup vs baseline: 2.2856x; 1.0119x over previous
#include <cuda_runtime.h>
#include <cuda_bf16.h>

// ---------------------------------------------------------------------------
// GNNEncoder: 2x GINEConv + global mean pool
//   N=200000, E=400000, G=4096; dims IN=128, HID=256, OUT=256, EDGE=16
// edge_index / batch arrive int32. batch is SORTED (exploited in pool).
// GEMMs: tf32 mma.sync, BM=128/BN=128/BK=32, 3-stage cp.async.
// ---------------------------------------------------------------------------

#define N_NODES 200000
#define N_EDGES 400000
#define N_GRAPHS 4096

__device__ float g_aggr[(size_t)N_NODES * 256];
__device__ float g_h1  [(size_t)N_NODES * 256];
__device__ float g_tmp [(size_t)N_NODES * 256];
__device__ float g_wr  [229376];
__device__ int   g_counts[N_GRAPHS];

#define O_W1A 0
#define O_W1B 32768
#define O_W2A 98304
#define O_W2B 163840

// ---------------------------------------------------------------------------
__global__ void zero_kernel(float4* __restrict__ p, long long n4) {
    long long i = (long long)blockIdx.x * blockDim.x + threadIdx.x;
    long long stride = (long long)gridDim.x * blockDim.x;
    float4 z = make_float4(0.f, 0.f, 0.f, 0.f);
    for (; i < n4; i += stride) p[i] = z;
}

__global__ void copy_kernel(const float4* __restrict__ src, float4* __restrict__ dst,
                            long long n4) {
    long long i = (long long)blockIdx.x * blockDim.x + threadIdx.x;
    long long stride = (long long)gridDim.x * blockDim.x;
    for (; i < n4; i += stride) dst[i] = src[i];
}

__device__ __forceinline__ float roundtf(float f) {
    unsigned u;
    asm("cvt.rna.tf32.f32 %0, %1;" : "=r"(u) : "f"(f));
    return __uint_as_float(u);
}

// One launch rounds all four weight matrices into g_wr (contiguous regions).
__global__ void round_all_kernel(const float* __restrict__ W1a,
                                 const float* __restrict__ W1b,
                                 const float* __restrict__ W2a,
                                 const float* __restrict__ W2b,
                                 float* __restrict__ dst) {
    int i = blockIdx.x * blockDim.x + threadIdx.x;
    if (i >= 229376) return;
    float v;
    if      (i < O_W1B) v = W1a[i - O_W1A];
    else if (i < O_W2A) v = W1b[i - O_W1B];
    else if (i < O_W2B) v = W2a[i - O_W2A];
    else                v = W2b[i - O_W2B];
    dst[i] = roundtf(v);
}

// ---------------------------------------------------------------------------
// Message + scatter:  aggr[dst] += relu(x[src] + edge_attr @ We + be)
// (aggr pre-initialized with x). One warp per 128-col chunk per edge.
// ---------------------------------------------------------------------------
template<int D>
__global__ __launch_bounds__(256)
void msg_scatter(const float* __restrict__ xin,
                 const float* __restrict__ ea,
                 const float* __restrict__ We,
                 const float* __restrict__ be,
                 const int* __restrict__ src_idx,
                 const int* __restrict__ dst_idx,
                 float* __restrict__ aggr, int E) {
    __shared__ float sWe[16 * D];
    __shared__ float sbe[D];
    for (int i = threadIdx.x; i < 16 * D; i += blockDim.x) sWe[i] = We[i];
    for (int i = threadIdx.x; i < D; i += blockDim.x) sbe[i] = be[i];
    __syncthreads();

    const int lane = threadIdx.x & 31;
    const int wid  = threadIdx.x >> 5;
    const int wpb  = blockDim.x >> 5;
    const int CH   = D / 128;
    const int NT   = E * CH;

    for (int t = blockIdx.x * wpb + wid; t < NT; t += gridDim.x * wpb) {
        int e, chunk;
        if (CH == 1) { e = t; chunk = 0; }
        else         { chunk = (t >= E) ? 1 : 0; e = t - chunk * E; }

        const long long s = src_idx[e];
        const long long d = dst_idx[e];

        float eav[16];
        const float4* eap = reinterpret_cast<const float4*>(ea + (long long)e * 16);
        #pragma unroll
        for (int q = 0; q < 4; q++) {
            float4 v = eap[q];
            eav[4*q+0] = v.x; eav[4*q+1] = v.y; eav[4*q+2] = v.z; eav[4*q+3] = v.w;
        }

        const int j = chunk * 128 + lane * 4;
        float4 p = *reinterpret_cast<const float4*>(sbe + j);
        #pragma unroll
        for (int k = 0; k < 16; k++) {
            const float4 w = *reinterpret_cast<const float4*>(sWe + k * D + j);
            p.x = fmaf(eav[k], w.x, p.x);
            p.y = fmaf(eav[k], w.y, p.y);
            p.z = fmaf(eav[k], w.z, p.z);
            p.w = fmaf(eav[k], w.w, p.w);
        }
        const float4 xv = *reinterpret_cast<const float4*>(xin + s * D + j);
        p.x = fmaxf(p.x + xv.x, 0.f);
        p.y = fmaxf(p.y + xv.y, 0.f);
        p.z = fmaxf(p.z + xv.z, 0.f);
        p.w = fmaxf(p.w + xv.w, 0.f);
        asm volatile("red.global.add.v4.f32 [%0], {%1,%2,%3,%4};"
                     :: "l"(aggr + d * D + j), "f"(p.x), "f"(p.y), "f"(p.z), "f"(p.w)
                     : "memory");
    }
}

// ---------------------------------------------------------------------------
// tf32 tensor-core GEMM: C = relu(A @ W + bias), optional dup-store C2.
// BM=128, BN=128, BK=32. 8 warps (2x4), warp tile 64x32. 3-stage cp.async.
// ---------------------------------------------------------------------------
__device__ __forceinline__ unsigned f2tf(float f) {
    unsigned u;
    asm("cvt.rna.tf32.f32 %0, %1;" : "=r"(u) : "f"(f));
    return u;
}
__device__ __forceinline__ void cp16(float* smem_dst, const float* gptr, int src_bytes) {
    unsigned saddr = (unsigned)__cvta_generic_to_shared(smem_dst);
    asm volatile("cp.async.cg.shared.global [%0], [%1], 16, %2;"
                 :: "r"(saddr), "l"(gptr), "r"(src_bytes));
}

#define ASTRIDE 36
#define BSTRIDE 136

template<bool AROUND, bool CROUND>
__global__ __launch_bounds__(256)
void gemm_tf32(const float* __restrict__ A, const float* __restrict__ W,
               const float* __restrict__ bias, float* __restrict__ C,
               float* __restrict__ C2, int M, int N, int K) {
    __shared__ float As[3][128 * ASTRIDE];   // 55.3 KB
    __shared__ float Bs[3][32 * BSTRIDE];    // 52.2 KB

    const int tid  = threadIdx.x;
    const int lane = tid & 31;
    const int wid  = tid >> 5;
    const int g    = lane >> 2;
    const int tig  = lane & 3;
    const int warpM = wid >> 2;       // 0..1 -> 64 rows each
    const int warpN = wid & 3;        // 0..3 -> 32 cols each

    const long long rowBase = (long long)blockIdx.y * 128;
    const int colBase = blockIdx.x * 128;

    // A loader: thread t -> row t>>1, 16 cols starting at (t&1)*16
    const int aRow = tid >> 1;
    const int aCol = (tid & 1) * 16;
    const bool aValid = (rowBase + aRow) < (long long)M;
    const float* aSrc = A + (rowBase + aRow) * K + aCol;
    // B loader: thread t -> row t>>3, 4 float4 chunks (t&7)+{0,8,16,24}
    const int bRow = tid >> 3;
    const int bC   = tid & 7;
    const float* bSrc = W + (long long)bRow * N + colBase;

    const int S = K >> 5;

    #pragma unroll
    for (int s = 0; s < 2; s++) {
        const int k0 = s * 32;
        #pragma unroll
        for (int q = 0; q < 4; q++)
            cp16(&As[s][aRow * ASTRIDE + aCol + q * 4], aSrc + k0 + q * 4, aValid ? 16 : 0);
        #pragma unroll
        for (int c = 0; c < 4; c++)
            cp16(&Bs[s][bRow * BSTRIDE + (bC + c * 8) * 4],
                 bSrc + (long long)k0 * N + (bC + c * 8) * 4, 16);
        asm volatile("cp.async.commit_group;");
    }

    float acc[4][4][4];
    #pragma unroll
    for (int i = 0; i < 4; i++)
        #pragma unroll
        for (int j = 0; j < 4; j++)
            #pragma unroll
            for (int r = 0; r < 4; r++) acc[i][j][r] = 0.f;

    for (int s = 0; s < S; s++) {
        asm volatile("cp.async.wait_group 1;");
        __syncthreads();

        const int sn = s + 2;
        if (sn < S) {
            const int buf = sn % 3;
            const int k0 = sn * 32;
            #pragma unroll
            for (int q = 0; q < 4; q++)
                cp16(&As[buf][aRow * ASTRIDE + aCol + q * 4], aSrc + k0 + q * 4, aValid ? 16 : 0);
            #pragma unroll
            for (int c = 0; c < 4; c++)
                cp16(&Bs[buf][bRow * BSTRIDE + (bC + c * 8) * 4],
                     bSrc + (long long)k0 * N + (bC + c * 8) * 4, 16);
        }
        asm volatile("cp.async.commit_group;");

        const float* as = As[s % 3];
        const float* bs = Bs[s % 3];

        #pragma unroll
        for (int kk = 0; kk < 4; kk++) {
            const int k = kk * 8;
            unsigned af[4][4], bf[4][2];
            #pragma unroll
            for (int i = 0; i < 4; i++) {
                const int r0 = warpM * 64 + i * 16 + g;
                if (AROUND) {
                    af[i][0] = __float_as_uint(as[(r0)     * ASTRIDE + k + tig]);
                    af[i][1] = __float_as_uint(as[(r0 + 8) * ASTRIDE + k + tig]);
                    af[i][2] = __float_as_uint(as[(r0)     * ASTRIDE + k + tig + 4]);
                    af[i][3] = __float_as_uint(as[(r0 + 8) * ASTRIDE + k + tig + 4]);
                } else {
                    af[i][0] = f2tf(as[(r0)     * ASTRIDE + k + tig]);
                    af[i][1] = f2tf(as[(r0 + 8) * ASTRIDE + k + tig]);
                    af[i][2] = f2tf(as[(r0)     * ASTRIDE + k + tig + 4]);
                    af[i][3] = f2tf(as[(r0 + 8) * ASTRIDE + k + tig + 4]);
                }
            }
            #pragma unroll
            for (int j = 0; j < 4; j++) {
                const int c0 = warpN * 32 + j * 8 + g;
                bf[j][0] = __float_as_uint(bs[(k + tig)     * BSTRIDE + c0]);
                bf[j][1] = __float_as_uint(bs[(k + tig + 4) * BSTRIDE + c0]);
            }
            #pragma unroll
            for (int i = 0; i < 4; i++)
                #pragma unroll
                for (int j = 0; j < 4; j++)
                    asm volatile(
                        "mma.sync.aligned.m16n8k8.row.col.f32.tf32.tf32.f32 "
                        "{%0,%1,%2,%3}, {%4,%5,%6,%7}, {%8,%9}, {%0,%1,%2,%3};"
                        : "+f"(acc[i][j][0]), "+f"(acc[i][j][1]),
                          "+f"(acc[i][j][2]), "+f"(acc[i][j][3])
                        : "r"(af[i][0]), "r"(af[i][1]), "r"(af[i][2]), "r"(af[i][3]),
                          "r"(bf[j][0]), "r"(bf[j][1]));
        }
    }

    #pragma unroll
    for (int j = 0; j < 4; j++) {
        const int col = colBase + warpN * 32 + j * 8 + 2 * tig;
        const float2 bv = *reinterpret_cast<const float2*>(bias + col);
        #pragma unroll
        for (int i = 0; i < 4; i++) {
            const long long r0 = rowBase + warpM * 64 + i * 16 + g;
            if (r0 < (long long)M) {
                float2 o;
                o.x = fmaxf(acc[i][j][0] + bv.x, 0.f);
                o.y = fmaxf(acc[i][j][1] + bv.y, 0.f);
                if (CROUND) { o.x = roundtf(o.x); o.y = roundtf(o.y); }
                *reinterpret_cast<float2*>(C + r0 * N + col) = o;
                if (C2) *reinterpret_cast<float2*>(C2 + r0 * N + col) = o;
            }
            const long long r1 = r0 + 8;
            if (r1 < (long long)M) {
                float2 o;
                o.x = fmaxf(acc[i][j][2] + bv.x, 0.f);
                o.y = fmaxf(acc[i][j][3] + bv.y, 0.f);
                if (CROUND) { o.x = roundtf(o.x); o.y = roundtf(o.y); }
                *reinterpret_cast<float2*>(C + r1 * N + col) = o;
                if (C2) *reinterpret_cast<float2*>(C2 + r1 * N + col) = o;
            }
        }
    }
}

// ---------------------------------------------------------------------------
// Global mean pool. batch is sorted: warp per 32-node strip, run-length
// accumulate in registers, one red dump per graph-run (~1.65/strip).
// ---------------------------------------------------------------------------
__global__ __launch_bounds__(256)
void pool_sorted(const float* __restrict__ h, const int* __restrict__ batch,
                 float* __restrict__ out, int* __restrict__ counts, int Nn) {
    const int lane = threadIdx.x & 31;
    const int wid  = threadIdx.x >> 5;
    const int strip = blockIdx.x * 8 + wid;
    const int n0 = strip * 32;
    if (n0 >= Nn) return;
    const int nEnd = min(n0 + 32, Nn);

    int cur = batch[n0];
    int run = 0;
    float4 a0 = make_float4(0.f, 0.f, 0.f, 0.f);
    float4 a1 = make_float4(0.f, 0.f, 0.f, 0.f);

    for (int n = n0; n < nEnd; n++) {
        const int b = batch[n];
        if (b != cur) {
            float* orow = out + (long long)cur * 256 + lane * 8;
            asm volatile("red.global.add.v4.f32 [%0], {%1,%2,%3,%4};"
                         :: "l"(orow), "f"(a0.x), "f"(a0.y), "f"(a0.z), "f"(a0.w) : "memory");
            asm volatile("red.global.add.v4.f32 [%0], {%1,%2,%3,%4};"
                         :: "l"(orow + 4), "f"(a1.x), "f"(a1.y), "f"(a1.z), "f"(a1.w) : "memory");
            if (lane == 0) atomicAdd(counts + cur, run);
            a0 = make_float4(0.f, 0.f, 0.f, 0.f);
            a1 = make_float4(0.f, 0.f, 0.f, 0.f);
            run = 0; cur = b;
        }
        const float4* r = reinterpret_cast<const float4*>(h + (long long)n * 256 + lane * 8);
        const float4 v0 = r[0], v1 = r[1];
        a0.x += v0.x; a0.y += v0.y; a0.z += v0.z; a0.w += v0.w;
        a1.x += v1.x; a1.y += v1.y; a1.z += v1.z; a1.w += v1.w;
        run++;
    }
    float* orow = out + (long long)cur * 256 + lane * 8;
    asm volatile("red.global.add.v4.f32 [%0], {%1,%2,%3,%4};"
                 :: "l"(orow), "f"(a0.x), "f"(a0.y), "f"(a0.z), "f"(a0.w) : "memory");
    asm volatile("red.global.add.v4.f32 [%0], {%1,%2,%3,%4};"
                 :: "l"(orow + 4), "f"(a1.x), "f"(a1.y), "f"(a1.z), "f"(a1.w) : "memory");
    if (lane == 0) atomicAdd(counts + cur, run);
}

__global__ void pool_div(float* __restrict__ out, const int* __restrict__ counts) {
    int idx = blockIdx.x * blockDim.x + threadIdx.x;
    if (idx < N_GRAPHS * 256) {
        float c = fmaxf((float)counts[idx >> 8], 1.f);
        out[idx] = out[idx] / c;
    }
}

// ---------------------------------------------------------------------------
extern "C" void kernel_launch(void* const* d_in, const int* in_sizes, int n_in,
                              void* d_out, int out_size) {
    const float* x    = (const float*)d_in[0];
    const float* ea   = (const float*)d_in[1];
    const float* We1  = (const float*)d_in[2];
    const float* be1  = (const float*)d_in[3];
    const float* W1a  = (const float*)d_in[4];
    const float* b1a  = (const float*)d_in[5];
    const float* W1b  = (const float*)d_in[6];
    const float* b1b  = (const float*)d_in[7];
    const float* We2  = (const float*)d_in[8];
    const float* be2  = (const float*)d_in[9];
    const float* W2a  = (const float*)d_in[10];
    const float* b2a  = (const float*)d_in[11];
    const float* W2b  = (const float*)d_in[12];
    const float* b2b  = (const float*)d_in[13];
    const int* eidx   = (const int*)d_in[14];   // int32
    const int* batch  = (const int*)d_in[15];   // int32 (sorted)
    float* out = (float*)d_out;

    float *aggr, *h1, *tmp, *wr;
    int* counts;
    cudaGetSymbolAddress((void**)&aggr,   g_aggr);
    cudaGetSymbolAddress((void**)&h1,     g_h1);
    cudaGetSymbolAddress((void**)&tmp,    g_tmp);
    cudaGetSymbolAddress((void**)&wr,     g_wr);
    cudaGetSymbolAddress((void**)&counts, g_counts);

    const int Nn = N_NODES, E = N_EDGES;
    const dim3 gemm_grid(2, (Nn + 127) / 128);   // BN=128 -> 2 col tiles

    // 1: round all weights in one launch
    round_all_kernel<<<(229376 + 255) / 256, 256>>>(W1a, W1b, W2a, W2b, wr);

    // ---- Layer 1 (D=128) ----
    copy_kernel<<<2048, 256>>>((const float4*)x, (float4*)aggr, (long long)Nn * 128 / 4); // 2
    msg_scatter<128><<<(E + 7) / 8, 256>>>(x, ea, We1, be1, eidx, eidx + E, aggr, E);     // 3
    gemm_tf32<false, true ><<<gemm_grid, 256>>>(aggr, wr + O_W1A, b1a, tmp, nullptr, Nn, 256, 128); // 4
    gemm_tf32<true,  false><<<gemm_grid, 256>>>(tmp, wr + O_W1B, b1b, h1, aggr, Nn, 256, 256);      // 5

    // ---- Layer 2 (D=256) ----
    msg_scatter<256><<<(2 * E + 7) / 8, 256>>>(h1, ea, We2, be2, eidx, eidx + E, aggr, E);          // 6 (ncu lands here)
    gemm_tf32<false, true ><<<gemm_grid, 256>>>(aggr, wr + O_W2A, b2a, tmp, nullptr, Nn, 256, 256); // 7
    gemm_tf32<true,  false><<<gemm_grid, 256>>>(tmp, wr + O_W2B, b2b, h1, nullptr, Nn, 256, 256);   // 8

    // ---- Global mean pool ----
    zero_kernel<<<1024, 256>>>((float4*)out, (long long)N_GRAPHS * 256 / 4);
    zero_kernel<<<4, 256>>>((float4*)counts, N_GRAPHS / 4);
    pool_sorted<<<(Nn / 32 + 7) / 8, 256>>>(h1, batch, out, counts, Nn);
    pool_div<<<(N_GRAPHS * 256 + 255) / 256, 256>>>(out, counts);
}

// round 11
// speedup vs baseline: 2.2859x; 1.0001x over previous
#include <cuda_runtime.h>
#include <cuda_bf16.h>

// ---------------------------------------------------------------------------
// GNNEncoder: 2x GINEConv + global mean pool
//   N=200000, E=400000, G=4096; dims IN=128, HID=256, OUT=256, EDGE=16
// edge_index / batch arrive int32. batch is SORTED (exploited in pool).
// GEMMs: tf32 mma.sync, BM=128/BN=128/BK=32, 2-stage cp.async, 2 CTAs/SM.
// ---------------------------------------------------------------------------

#define N_NODES 200000
#define N_EDGES 400000
#define N_GRAPHS 4096

__device__ float g_aggr[(size_t)N_NODES * 256];
__device__ float g_h1  [(size_t)N_NODES * 256];
__device__ float g_tmp [(size_t)N_NODES * 256];
__device__ float g_wr  [229376];
__device__ int   g_counts[N_GRAPHS];

#define O_W1A 0
#define O_W1B 32768
#define O_W2A 98304
#define O_W2B 163840

// ---------------------------------------------------------------------------
__global__ void zero_kernel(float4* __restrict__ p, long long n4) {
    long long i = (long long)blockIdx.x * blockDim.x + threadIdx.x;
    long long stride = (long long)gridDim.x * blockDim.x;
    float4 z = make_float4(0.f, 0.f, 0.f, 0.f);
    for (; i < n4; i += stride) p[i] = z;
}

__global__ void copy_kernel(const float4* __restrict__ src, float4* __restrict__ dst,
                            long long n4) {
    long long i = (long long)blockIdx.x * blockDim.x + threadIdx.x;
    long long stride = (long long)gridDim.x * blockDim.x;
    for (; i < n4; i += stride) dst[i] = src[i];
}

__device__ __forceinline__ float roundtf(float f) {
    unsigned u;
    asm("cvt.rna.tf32.f32 %0, %1;" : "=r"(u) : "f"(f));
    return __uint_as_float(u);
}

__global__ void round_all_kernel(const float* __restrict__ W1a,
                                 const float* __restrict__ W1b,
                                 const float* __restrict__ W2a,
                                 const float* __restrict__ W2b,
                                 float* __restrict__ dst) {
    int i = blockIdx.x * blockDim.x + threadIdx.x;
    if (i >= 229376) return;
    float v;
    if      (i < O_W1B) v = W1a[i - O_W1A];
    else if (i < O_W2A) v = W1b[i - O_W1B];
    else if (i < O_W2B) v = W2a[i - O_W2A];
    else                v = W2b[i - O_W2B];
    dst[i] = roundtf(v);
}

// ---------------------------------------------------------------------------
// Message + scatter:  aggr[dst] += relu(x[src] + edge_attr @ We + be)
// (aggr pre-initialized with x). One warp per 128-col chunk per edge.
// ---------------------------------------------------------------------------
template<int D>
__global__ __launch_bounds__(256)
void msg_scatter(const float* __restrict__ xin,
                 const float* __restrict__ ea,
                 const float* __restrict__ We,
                 const float* __restrict__ be,
                 const int* __restrict__ src_idx,
                 const int* __restrict__ dst_idx,
                 float* __restrict__ aggr, int E) {
    __shared__ float sWe[16 * D];
    __shared__ float sbe[D];
    for (int i = threadIdx.x; i < 16 * D; i += blockDim.x) sWe[i] = We[i];
    for (int i = threadIdx.x; i < D; i += blockDim.x) sbe[i] = be[i];
    __syncthreads();

    const int lane = threadIdx.x & 31;
    const int wid  = threadIdx.x >> 5;
    const int wpb  = blockDim.x >> 5;
    const int CH   = D / 128;
    const int NT   = E * CH;

    for (int t = blockIdx.x * wpb + wid; t < NT; t += gridDim.x * wpb) {
        int e, chunk;
        if (CH == 1) { e = t; chunk = 0; }
        else         { chunk = (t >= E) ? 1 : 0; e = t - chunk * E; }

        const long long s = src_idx[e];
        const long long d = dst_idx[e];

        float eav[16];
        const float4* eap = reinterpret_cast<const float4*>(ea + (long long)e * 16);
        #pragma unroll
        for (int q = 0; q < 4; q++) {
            float4 v = eap[q];
            eav[4*q+0] = v.x; eav[4*q+1] = v.y; eav[4*q+2] = v.z; eav[4*q+3] = v.w;
        }

        const int j = chunk * 128 + lane * 4;
        float4 p = *reinterpret_cast<const float4*>(sbe + j);
        #pragma unroll
        for (int k = 0; k < 16; k++) {
            const float4 w = *reinterpret_cast<const float4*>(sWe + k * D + j);
            p.x = fmaf(eav[k], w.x, p.x);
            p.y = fmaf(eav[k], w.y, p.y);
            p.z = fmaf(eav[k], w.z, p.z);
            p.w = fmaf(eav[k], w.w, p.w);
        }
        const float4 xv = *reinterpret_cast<const float4*>(xin + s * D + j);
        p.x = fmaxf(p.x + xv.x, 0.f);
        p.y = fmaxf(p.y + xv.y, 0.f);
        p.z = fmaxf(p.z + xv.z, 0.f);
        p.w = fmaxf(p.w + xv.w, 0.f);
        asm volatile("red.global.add.v4.f32 [%0], {%1,%2,%3,%4};"
                     :: "l"(aggr + d * D + j), "f"(p.x), "f"(p.y), "f"(p.z), "f"(p.w)
                     : "memory");
    }
}

// ---------------------------------------------------------------------------
// tf32 tensor-core GEMM: C = relu(A @ W + bias), optional dup-store C2.
// BM=128, BN=128, BK=32. 8 warps (2x4), warp tile 64x32.
// 2-stage double buffer (71.7 KB smem) -> 2 CTAs/SM for latency hiding.
// ---------------------------------------------------------------------------
__device__ __forceinline__ unsigned f2tf(float f) {
    unsigned u;
    asm("cvt.rna.tf32.f32 %0, %1;" : "=r"(u) : "f"(f));
    return u;
}
__device__ __forceinline__ void cp16(float* smem_dst, const float* gptr, int src_bytes) {
    unsigned saddr = (unsigned)__cvta_generic_to_shared(smem_dst);
    asm volatile("cp.async.cg.shared.global [%0], [%1], 16, %2;"
                 :: "r"(saddr), "l"(gptr), "r"(src_bytes));
}

#define ASTRIDE 36
#define BSTRIDE 136

template<bool AROUND, bool CROUND>
__global__ __launch_bounds__(256, 2)
void gemm_tf32(const float* __restrict__ A, const float* __restrict__ W,
               const float* __restrict__ bias, float* __restrict__ C,
               float* __restrict__ C2, int M, int N, int K) {
    __shared__ float As[2][128 * ASTRIDE];   // 36.9 KB
    __shared__ float Bs[2][32 * BSTRIDE];    // 34.8 KB

    const int tid  = threadIdx.x;
    const int lane = tid & 31;
    const int wid  = tid >> 5;
    const int g    = lane >> 2;
    const int tig  = lane & 3;
    const int warpM = wid >> 2;       // 0..1 -> 64 rows each
    const int warpN = wid & 3;        // 0..3 -> 32 cols each

    const long long rowBase = (long long)blockIdx.y * 128;
    const int colBase = blockIdx.x * 128;

    // A loader: thread t -> row t>>1, 16 cols starting at (t&1)*16
    const int aRow = tid >> 1;
    const int aCol = (tid & 1) * 16;
    const bool aValid = (rowBase + aRow) < (long long)M;
    const float* aSrc = A + (rowBase + aRow) * K + aCol;
    // B loader: thread t -> row t>>3, 4 float4 chunks (t&7)+{0,8,16,24}
    const int bRow = tid >> 3;
    const int bC   = tid & 7;
    const float* bSrc = W + (long long)bRow * N + colBase;

    const int S = K >> 5;

    // prologue: stage 0
    {
        #pragma unroll
        for (int q = 0; q < 4; q++)
            cp16(&As[0][aRow * ASTRIDE + aCol + q * 4], aSrc + q * 4, aValid ? 16 : 0);
        #pragma unroll
        for (int c = 0; c < 4; c++)
            cp16(&Bs[0][bRow * BSTRIDE + (bC + c * 8) * 4],
                 bSrc + (long long)(bC + c * 8) * 4, 16);
        asm volatile("cp.async.commit_group;");
    }

    float acc[4][4][4];
    #pragma unroll
    for (int i = 0; i < 4; i++)
        #pragma unroll
        for (int j = 0; j < 4; j++)
            #pragma unroll
            for (int r = 0; r < 4; r++) acc[i][j][r] = 0.f;

    for (int s = 0; s < S; s++) {
        asm volatile("cp.async.wait_group 0;");
        __syncthreads();   // stage s visible to all; prior compute done (safe to overwrite other buf)

        const int sn = s + 1;
        if (sn < S) {
            const int buf = sn & 1;
            const int k0 = sn * 32;
            #pragma unroll
            for (int q = 0; q < 4; q++)
                cp16(&As[buf][aRow * ASTRIDE + aCol + q * 4], aSrc + k0 + q * 4, aValid ? 16 : 0);
            #pragma unroll
            for (int c = 0; c < 4; c++)
                cp16(&Bs[buf][bRow * BSTRIDE + (bC + c * 8) * 4],
                     bSrc + (long long)k0 * N + (bC + c * 8) * 4, 16);
        }
        asm volatile("cp.async.commit_group;");

        const float* as = As[s & 1];
        const float* bs = Bs[s & 1];

        #pragma unroll
        for (int kk = 0; kk < 4; kk++) {
            const int k = kk * 8;
            unsigned af[4][4], bf[4][2];
            #pragma unroll
            for (int i = 0; i < 4; i++) {
                const int r0 = warpM * 64 + i * 16 + g;
                if (AROUND) {
                    af[i][0] = __float_as_uint(as[(r0)     * ASTRIDE + k + tig]);
                    af[i][1] = __float_as_uint(as[(r0 + 8) * ASTRIDE + k + tig]);
                    af[i][2] = __float_as_uint(as[(r0)     * ASTRIDE + k + tig + 4]);
                    af[i][3] = __float_as_uint(as[(r0 + 8) * ASTRIDE + k + tig + 4]);
                } else {
                    af[i][0] = f2tf(as[(r0)     * ASTRIDE + k + tig]);
                    af[i][1] = f2tf(as[(r0 + 8) * ASTRIDE + k + tig]);
                    af[i][2] = f2tf(as[(r0)     * ASTRIDE + k + tig + 4]);
                    af[i][3] = f2tf(as[(r0 + 8) * ASTRIDE + k + tig + 4]);
                }
            }
            #pragma unroll
            for (int j = 0; j < 4; j++) {
                const int c0 = warpN * 32 + j * 8 + g;
                bf[j][0] = __float_as_uint(bs[(k + tig)     * BSTRIDE + c0]);
                bf[j][1] = __float_as_uint(bs[(k + tig + 4) * BSTRIDE + c0]);
            }
            #pragma unroll
            for (int i = 0; i < 4; i++)
                #pragma unroll
                for (int j = 0; j < 4; j++)
                    asm volatile(
                        "mma.sync.aligned.m16n8k8.row.col.f32.tf32.tf32.f32 "
                        "{%0,%1,%2,%3}, {%4,%5,%6,%7}, {%8,%9}, {%0,%1,%2,%3};"
                        : "+f"(acc[i][j][0]), "+f"(acc[i][j][1]),
                          "+f"(acc[i][j][2]), "+f"(acc[i][j][3])
                        : "r"(af[i][0]), "r"(af[i][1]), "r"(af[i][2]), "r"(af[i][3]),
                          "r"(bf[j][0]), "r"(bf[j][1]));
        }
    }

    #pragma unroll
    for (int j = 0; j < 4; j++) {
        const int col = colBase + warpN * 32 + j * 8 + 2 * tig;
        const float2 bv = *reinterpret_cast<const float2*>(bias + col);
        #pragma unroll
        for (int i = 0; i < 4; i++) {
            const long long r0 = rowBase + warpM * 64 + i * 16 + g;
            if (r0 < (long long)M) {
                float2 o;
                o.x = fmaxf(acc[i][j][0] + bv.x, 0.f);
                o.y = fmaxf(acc[i][j][1] + bv.y, 0.f);
                if (CROUND) { o.x = roundtf(o.x); o.y = roundtf(o.y); }
                *reinterpret_cast<float2*>(C + r0 * N + col) = o;
                if (C2) *reinterpret_cast<float2*>(C2 + r0 * N + col) = o;
            }
            const long long r1 = r0 + 8;
            if (r1 < (long long)M) {
                float2 o;
                o.x = fmaxf(acc[i][j][2] + bv.x, 0.f);
                o.y = fmaxf(acc[i][j][3] + bv.y, 0.f);
                if (CROUND) { o.x = roundtf(o.x); o.y = roundtf(o.y); }
                *reinterpret_cast<float2*>(C + r1 * N + col) = o;
                if (C2) *reinterpret_cast<float2*>(C2 + r1 * N + col) = o;
            }
        }
    }
}

// ---------------------------------------------------------------------------
// Global mean pool. batch sorted: warp per 32-node strip, run-length
// accumulate, one red dump per graph-run.
// ---------------------------------------------------------------------------
__global__ __launch_bounds__(256)
void pool_sorted(const float* __restrict__ h, const int* __restrict__ batch,
                 float* __restrict__ out, int* __restrict__ counts, int Nn) {
    const int lane = threadIdx.x & 31;
    const int wid  = threadIdx.x >> 5;
    const int strip = blockIdx.x * 8 + wid;
    const int n0 = strip * 32;
    if (n0 >= Nn) return;
    const int nEnd = min(n0 + 32, Nn);

    int cur = batch[n0];
    int run = 0;
    float4 a0 = make_float4(0.f, 0.f, 0.f, 0.f);
    float4 a1 = make_float4(0.f, 0.f, 0.f, 0.f);

    for (int n = n0; n < nEnd; n++) {
        const int b = batch[n];
        if (b != cur) {
            float* orow = out + (long long)cur * 256 + lane * 8;
            asm volatile("red.global.add.v4.f32 [%0], {%1,%2,%3,%4};"
                         :: "l"(orow), "f"(a0.x), "f"(a0.y), "f"(a0.z), "f"(a0.w) : "memory");
            asm volatile("red.global.add.v4.f32 [%0], {%1,%2,%3,%4};"
                         :: "l"(orow + 4), "f"(a1.x), "f"(a1.y), "f"(a1.z), "f"(a1.w) : "memory");
            if (lane == 0) atomicAdd(counts + cur, run);
            a0 = make_float4(0.f, 0.f, 0.f, 0.f);
            a1 = make_float4(0.f, 0.f, 0.f, 0.f);
            run = 0; cur = b;
        }
        const float4* r = reinterpret_cast<const float4*>(h + (long long)n * 256 + lane * 8);
        const float4 v0 = r[0], v1 = r[1];
        a0.x += v0.x; a0.y += v0.y; a0.z += v0.z; a0.w += v0.w;
        a1.x += v1.x; a1.y += v1.y; a1.z += v1.z; a1.w += v1.w;
        run++;
    }
    float* orow = out + (long long)cur * 256 + lane * 8;
    asm volatile("red.global.add.v4.f32 [%0], {%1,%2,%3,%4};"
                 :: "l"(orow), "f"(a0.x), "f"(a0.y), "f"(a0.z), "f"(a0.w) : "memory");
    asm volatile("red.global.add.v4.f32 [%0], {%1,%2,%3,%4};"
                 :: "l"(orow + 4), "f"(a1.x), "f"(a1.y), "f"(a1.z), "f"(a1.w) : "memory");
    if (lane == 0) atomicAdd(counts + cur, run);
}

__global__ void pool_div(float* __restrict__ out, const int* __restrict__ counts) {
    int idx = blockIdx.x * blockDim.x + threadIdx.x;
    if (idx < N_GRAPHS * 256) {
        float c = fmaxf((float)counts[idx >> 8], 1.f);
        out[idx] = out[idx] / c;
    }
}

// ---------------------------------------------------------------------------
extern "C" void kernel_launch(void* const* d_in, const int* in_sizes, int n_in,
                              void* d_out, int out_size) {
    const float* x    = (const float*)d_in[0];
    const float* ea   = (const float*)d_in[1];
    const float* We1  = (const float*)d_in[2];
    const float* be1  = (const float*)d_in[3];
    const float* W1a  = (const float*)d_in[4];
    const float* b1a  = (const float*)d_in[5];
    const float* W1b  = (const float*)d_in[6];
    const float* b1b  = (const float*)d_in[7];
    const float* We2  = (const float*)d_in[8];
    const float* be2  = (const float*)d_in[9];
    const float* W2a  = (const float*)d_in[10];
    const float* b2a  = (const float*)d_in[11];
    const float* W2b  = (const float*)d_in[12];
    const float* b2b  = (const float*)d_in[13];
    const int* eidx   = (const int*)d_in[14];   // int32
    const int* batch  = (const int*)d_in[15];   // int32 (sorted)
    float* out = (float*)d_out;

    float *aggr, *h1, *tmp, *wr;
    int* counts;
    cudaGetSymbolAddress((void**)&aggr,   g_aggr);
    cudaGetSymbolAddress((void**)&h1,     g_h1);
    cudaGetSymbolAddress((void**)&tmp,    g_tmp);
    cudaGetSymbolAddress((void**)&wr,     g_wr);
    cudaGetSymbolAddress((void**)&counts, g_counts);

    const int Nn = N_NODES, E = N_EDGES;
    const dim3 gemm_grid(2, (Nn + 127) / 128);   // BN=128 -> 2 col tiles

    round_all_kernel<<<(229376 + 255) / 256, 256>>>(W1a, W1b, W2a, W2b, wr);

    // ---- Layer 1 (D=128) ----
    copy_kernel<<<2048, 256>>>((const float4*)x, (float4*)aggr, (long long)Nn * 128 / 4);
    msg_scatter<128><<<(E + 7) / 8, 256>>>(x, ea, We1, be1, eidx, eidx + E, aggr, E);
    gemm_tf32<false, true ><<<gemm_grid, 256>>>(aggr, wr + O_W1A, b1a, tmp, nullptr, Nn, 256, 128);
    gemm_tf32<true,  false><<<gemm_grid, 256>>>(tmp, wr + O_W1B, b1b, h1, aggr, Nn, 256, 256);

    // ---- Layer 2 (D=256) ----
    msg_scatter<256><<<(2 * E + 7) / 8, 256>>>(h1, ea, We2, be2, eidx, eidx + E, aggr, E);
    gemm_tf32<false, true ><<<gemm_grid, 256>>>(aggr, wr + O_W2A, b2a, tmp, nullptr, Nn, 256, 256);
    gemm_tf32<true,  false><<<gemm_grid, 256>>>(tmp, wr + O_W2B, b2b, h1, nullptr, Nn, 256, 256);

    // ---- Global mean pool ----
    zero_kernel<<<1024, 256>>>((float4*)out, (long long)N_GRAPHS * 256 / 4);
    zero_kernel<<<4, 256>>>((float4*)counts, N_GRAPHS / 4);
    pool_sorted<<<(Nn / 32 + 7) / 8, 256>>>(h1, batch, out, counts, Nn);
    pool_div<<<(N_GRAPHS * 256 + 255) / 256, 256>>>(out, counts);
}